// round 2
// baseline (speedup 1.0000x reference)
#include <cuda_runtime.h>
#include <math.h>

#define FULLMASK 0xffffffffu

// Coefficients of k_1..k_{s+1} used to build the input of the NEXT stage
// (rows 0..4 = A-rows 2..6, row 5 = B row for the final update).
__constant__ float CT[6][6] = {
    {0.161f, 0.f, 0.f, 0.f, 0.f, 0.f},
    {(float)(-0.008480655492356989), (float)(0.335480655492357), 0.f, 0.f, 0.f, 0.f},
    {(float)(2.8971530571054935), (float)(-6.359448489975075), (float)(4.3622954328695815), 0.f, 0.f, 0.f},
    {(float)(5.325864828439257), (float)(-11.748883564062828), (float)(7.4955393428898365), (float)(-0.09249506636175525), 0.f, 0.f},
    {(float)(5.86145544294642), (float)(-12.92096931784711), (float)(8.159367898576159), (float)(-0.071584973281401), (float)(-0.028269050394068383), 0.f},
    {(float)(0.09646076681806523), 0.01f, (float)(0.4798896504144996), (float)(1.379008574103742), (float)(-3.290069515436081), (float)(2.324710524099774)}
};

static __device__ __forceinline__ float softplus_f(float x) {
    // matches jax.nn.softplus = max(x,0) + log1p(exp(-|x|))
    return fmaxf(x, 0.0f) + log1pf(expf(-fabsf(x)));
}
static __device__ __forceinline__ float sigmoid_f(float x) {
    return 1.0f / (1.0f + expf(-x));
}

// State layout in all shared vectors: [0..63] = h (hidden), [64..68] = S,E,I,A,R
__global__ __launch_bounds__(256, 1)
void ode_persistent_kernel(
    const float* __restrict__ y0,   const float* __restrict__ ts,
    const float* __restrict__ gW0,  const float* __restrict__ gb0,
    const float* __restrict__ gW1,  const float* __restrict__ gb1,
    const float* __restrict__ gW2,  const float* __restrict__ gb2,
    const float* __restrict__ gW3,  const float* __restrict__ gb3,
    const float* __restrict__ gWhb, const float* __restrict__ gbhb,
    const float* __restrict__ ghv,  const float* __restrict__ gscale,
    float* __restrict__ out)
{
    const int t    = threadIdx.x;
    const int r01  = t >> 1;        // row for W0 / W1 / W2 (0..127)
    const int hf   = t & 1;         // which half of the dot product
    const int r3   = t >> 2;        // row for W3 (0..63)
    const int q3   = t & 3;         // which quarter of the W3 dot
    const int warp = t >> 5;
    const int lane = t & 31;

    __shared__ __align__(16) float syin[72];   // current rhs input vector
    __shared__ __align__(16) float sy[72];     // base y of the current step
    __shared__ __align__(16) float sk[6][72];  // k_1..k_6
    __shared__ __align__(16) float sza[128];   // activation ping
    __shared__ __align__(16) float szb[128];   // activation pong
    __shared__ __align__(16) float swhb[64];
    __shared__ float sdt[200];

    float* out_state = out;          // (201, 5)
    float* out_h     = out + 201*5;  // (201, 64)

    // ---- load weights into registers (stay resident for the whole run) ----
    float w0[32], w1[64], w2[64], w3[32];
    {
        const float4* p0 = reinterpret_cast<const float4*>(gW0 + (r01 * 64 + hf * 32));
        #pragma unroll
        for (int j = 0; j < 8; j++) {
            float4 v = p0[j];
            w0[4*j+0] = v.x; w0[4*j+1] = v.y; w0[4*j+2] = v.z; w0[4*j+3] = v.w;
        }
        const float4* p1 = reinterpret_cast<const float4*>(gW1 + (r01 * 128 + hf * 64));
        #pragma unroll
        for (int j = 0; j < 16; j++) {
            float4 v = p1[j];
            w1[4*j+0] = v.x; w1[4*j+1] = v.y; w1[4*j+2] = v.z; w1[4*j+3] = v.w;
        }
        const float4* p2 = reinterpret_cast<const float4*>(gW2 + (r01 * 128 + hf * 64));
        #pragma unroll
        for (int j = 0; j < 16; j++) {
            float4 v = p2[j];
            w2[4*j+0] = v.x; w2[4*j+1] = v.y; w2[4*j+2] = v.z; w2[4*j+3] = v.w;
        }
        const float4* p3 = reinterpret_cast<const float4*>(gW3 + (r3 * 128 + q3 * 32));
        #pragma unroll
        for (int j = 0; j < 8; j++) {
            float4 v = p3[j];
            w3[4*j+0] = v.x; w3[4*j+1] = v.y; w3[4*j+2] = v.z; w3[4*j+3] = v.w;
        }
    }
    const float rb0 = gb0[r01];
    const float rb1 = gb1[r01];
    const float rb2 = gb2[r01];
    const float rb3 = gb3[r3];
    const float bhb = gbhb[0];
    const float scl = gscale[0];

    // ---- init state / dt table / initial save ----
    if (t < 64) {
        float hv = ghv[t];
        sy[t] = hv; syin[t] = hv;
        out_h[t] = hv;              // save index 0, hidden part
        swhb[t] = gWhb[t];
    } else if (t < 69) {
        float v = y0[t - 64];
        sy[t] = v; syin[t] = v;
        out_state[t - 64] = v;      // save index 0, state part
    }
    #pragma unroll 1
    for (int i = t; i < 200; i += 256) sdt[i] = (ts[i + 1] - ts[i]) * 0.02f;
    __syncthreads();

    // ---- main sequential integration ----
    #pragma unroll 1
    for (int iv = 0; iv < 200; iv++) {
        const float dt = sdt[iv];
        const int sidx = iv + 1;
        #pragma unroll 1
        for (int sub = 0; sub < 50; sub++) {
            const bool save = (sub == 49);
            #pragma unroll 1
            for (int s = 0; s < 6; s++) {
                // ===== Phase A: z0 = softplus(W0 @ h + b0) =====
                {
                    float a0 = 0.f, a1 = 0.f, a2 = 0.f, a3 = 0.f;
                    const float* hin = syin + hf * 32;
                    #pragma unroll
                    for (int j = 0; j < 32; j += 4) {
                        float4 z = *reinterpret_cast<const float4*>(hin + j);
                        a0 = fmaf(w0[j+0], z.x, a0);
                        a1 = fmaf(w0[j+1], z.y, a1);
                        a2 = fmaf(w0[j+2], z.z, a2);
                        a3 = fmaf(w0[j+3], z.w, a3);
                    }
                    float sacc = (a0 + a1) + (a2 + a3);
                    sacc += __shfl_xor_sync(FULLMASK, sacc, 1);
                    if (hf == 0) sza[r01] = softplus_f(sacc + rb0);
                }
                __syncthreads();

                // ===== Phase B: z1 = softplus(W1 @ z0 + b1); warp7: beta + dstate =====
                {
                    float a0 = 0.f, a1 = 0.f, a2 = 0.f, a3 = 0.f;
                    const float* zin = sza + hf * 64;
                    #pragma unroll
                    for (int j = 0; j < 64; j += 4) {
                        float4 z = *reinterpret_cast<const float4*>(zin + j);
                        a0 = fmaf(w1[j+0], z.x, a0);
                        a1 = fmaf(w1[j+1], z.y, a1);
                        a2 = fmaf(w1[j+2], z.z, a2);
                        a3 = fmaf(w1[j+3], z.w, a3);
                    }
                    float sacc = (a0 + a1) + (a2 + a3);
                    sacc += __shfl_xor_sync(FULLMASK, sacc, 1);
                    if (hf == 0) szb[r01] = softplus_f(sacc + rb1);

                    if (warp == 7) {
                        // beta = sigmoid(Whb @ h + bhb), computed redundantly per lane
                        float c0 = 0.f, c1 = 0.f, c2 = 0.f, c3 = 0.f;
                        #pragma unroll
                        for (int j = 0; j < 64; j += 4) {
                            float4 hh = *reinterpret_cast<const float4*>(syin + j);
                            float4 wv = *reinterpret_cast<const float4*>(swhb + j);
                            c0 = fmaf(wv.x, hh.x, c0);
                            c1 = fmaf(wv.y, hh.y, c1);
                            c2 = fmaf(wv.z, hh.z, c2);
                            c3 = fmaf(wv.w, hh.w, c3);
                        }
                        float beta = sigmoid_f((c0 + c1) + (c2 + c3) + bhb);
                        if (lane == 0) {
                            float Sv = syin[64], Ev = syin[65], Iv = syin[66], Av = syin[67];
                            float LL  = 0.5f * Iv + Av;             // ee=0, (1-q)=0.5, dd=1
                            float bsl = (beta * Sv) * LL;
                            sk[s][64] = -bsl;                                        // dS
                            sk[s][65] = bsl - 0.526f * Ev;                           // dE
                            sk[s][66] = (float)(0.667 * 0.526) * Ev - 0.244f * Iv;   // dI
                            sk[s][67] = (float)((1.0 - 0.667) * 0.526) * Ev - 0.244f * Av; // dA
                            sk[s][68] = (float)(0.98 * 0.244) * Iv + 0.244f * Av;    // dR
                        }
                    }
                }
                __syncthreads();

                // ===== Phase C: z2 = softplus(W2 @ z1 + b2) =====
                {
                    float a0 = 0.f, a1 = 0.f, a2 = 0.f, a3 = 0.f;
                    const float* zin = szb + hf * 64;
                    #pragma unroll
                    for (int j = 0; j < 64; j += 4) {
                        float4 z = *reinterpret_cast<const float4*>(zin + j);
                        a0 = fmaf(w2[j+0], z.x, a0);
                        a1 = fmaf(w2[j+1], z.y, a1);
                        a2 = fmaf(w2[j+2], z.z, a2);
                        a3 = fmaf(w2[j+3], z.w, a3);
                    }
                    float sacc = (a0 + a1) + (a2 + a3);
                    sacc += __shfl_xor_sync(FULLMASK, sacc, 1);
                    if (hf == 0) sza[r01] = softplus_f(sacc + rb2);
                }
                __syncthreads();

                // ===== Phase D: o = W3 @ z2 + b3; dh; write k_s and next-stage input =====
                {
                    float a0 = 0.f, a1 = 0.f, a2 = 0.f, a3 = 0.f;
                    const float* zin = sza + q3 * 32;
                    #pragma unroll
                    for (int j = 0; j < 32; j += 4) {
                        float4 z = *reinterpret_cast<const float4*>(zin + j);
                        a0 = fmaf(w3[j+0], z.x, a0);
                        a1 = fmaf(w3[j+1], z.y, a1);
                        a2 = fmaf(w3[j+2], z.z, a2);
                        a3 = fmaf(w3[j+3], z.w, a3);
                    }
                    float sacc = (a0 + a1) + (a2 + a3);
                    sacc += __shfl_xor_sync(FULLMASK, sacc, 1);
                    sacc += __shfl_xor_sync(FULLMASK, sacc, 2);

                    if (q3 == 0) {
                        float o  = sacc + rb3;
                        float kc = scl * tanhf(1e-4f * o);
                        sk[s][r3] = kc;
                        float comb = CT[s][s] * kc;
                        #pragma unroll 1
                        for (int i = 0; i < s; i++) comb = fmaf(CT[s][i], sk[i][r3], comb);
                        float yn = fmaf(dt, comb, sy[r3]);
                        syin[r3] = yn;
                        if (s == 5) {
                            sy[r3] = yn;
                            if (save) out_h[sidx * 64 + r3] = yn;
                        }
                    } else if (q3 == 1 && r3 < 5) {
                        int j = 64 + r3;
                        float kc = sk[s][j];   // written in phase B, visible after C's barrier
                        float comb = CT[s][s] * kc;
                        #pragma unroll 1
                        for (int i = 0; i < s; i++) comb = fmaf(CT[s][i], sk[i][j], comb);
                        float yn = fmaf(dt, comb, sy[j]);
                        syin[j] = yn;
                        if (s == 5) {
                            sy[j] = yn;
                            if (save) out_state[sidx * 5 + r3] = yn;
                        }
                    }
                }
                __syncthreads();
            } // stages
        } // substeps
    } // intervals
}

extern "C" void kernel_launch(void* const* d_in, const int* in_sizes, int n_in,
                              void* d_out, int out_size) {
    (void)in_sizes; (void)n_in; (void)out_size;
    const float* y0   = (const float*)d_in[0];
    const float* ts   = (const float*)d_in[1];
    const float* W0   = (const float*)d_in[2];
    const float* b0   = (const float*)d_in[3];
    const float* W1   = (const float*)d_in[4];
    const float* b1   = (const float*)d_in[5];
    const float* W2   = (const float*)d_in[6];
    const float* b2   = (const float*)d_in[7];
    const float* W3   = (const float*)d_in[8];
    const float* b3   = (const float*)d_in[9];
    const float* Whb  = (const float*)d_in[10];
    const float* bhb  = (const float*)d_in[11];
    const float* hv   = (const float*)d_in[12];
    const float* scal = (const float*)d_in[13];
    float* out = (float*)d_out;

    ode_persistent_kernel<<<1, 256>>>(y0, ts, W0, b0, W1, b1, W2, b2, W3, b3,
                                      Whb, bhb, hv, scal, out);
}